// round 3
// baseline (speedup 1.0000x reference)
#include <cuda_runtime.h>

// Heirachical_Loss: loss = sum_i (1 - win_i)
// win_i = 0.5*S_all + 0.25*S100 + 0.125*S10 + 0.125*x[i,t]
// B=32768 rows, C=1000 fp32 classes. HBM-streaming bound.
// All 9 loads per warp issued up-front (single memory wait phase, MLP=9).

#define NROWS 32768
#define NCOLS 1000
#define ROWS_PER_BLOCK 8
#define NBLOCKS (NROWS / ROWS_PER_BLOCK)   // 4096
#define BLOCK_THREADS 256

__device__ float g_partials[NBLOCKS];
__device__ unsigned int g_count;           // zero-init; reset by last block each call

#define ADD_F32X2(acc, v) \
    asm("add.rn.f32x2 %0, %0, %1;" : "+l"(acc) : "l"(v))

__global__ void __launch_bounds__(BLOCK_THREADS, 4)   // allow 64 regs: keep loads batched
hloss_fused(const float* __restrict__ outputs, const int* __restrict__ target,
            float* __restrict__ out) {
    const int warp = threadIdx.x >> 5;
    const int lane = threadIdx.x & 31;
    const int row  = blockIdx.x * ROWS_PER_BLOCK + warp;

    const float* __restrict__ rowf = outputs + (size_t)row * NCOLS;
    const ulonglong2* __restrict__ rowp = reinterpret_cast<const ulonglong2*>(rowf);

    const int t = target[row];
    const int g100lo = (t / 100) * 100;     // multiple of 100 (4-aligned)
    const int g10lo  = (t / 10)  * 10;

    // ---- Issue ALL loads up front: 7 full + tail + pass-2 subset ----
    ulonglong2 v[7];
#pragma unroll
    for (int i = 0; i < 7; ++i)
        v[i] = rowp[lane + i * 32];                     // float indices 0..895

    ulonglong2 vt = {0ull, 0ull};
    if (lane < 26)                                       // float4 indices 224..249
        vt = rowp[224 + lane];

    float4 v100 = {0.f, 0.f, 0.f, 0.f};
    if (lane < 25)                                       // 100-group subset (L1 sector-merged)
        v100 = reinterpret_cast<const float4*>(rowf + g100lo)[lane];

    // ---- S_all: packed f32x2 adds ----
    unsigned long long a0 = 0ull, a1 = 0ull;
#pragma unroll
    for (int i = 0; i < 7; ++i) {
        ADD_F32X2(a0, v[i].x);
        ADD_F32X2(a1, v[i].y);
    }
    ADD_F32X2(a0, vt.x);        // zeros for lane >= 26
    ADD_F32X2(a1, vt.y);

    float s_all;
    {
        float r0, r1, r2, r3;
        asm("mov.b64 {%0, %1}, %2;" : "=f"(r0), "=f"(r1) : "l"(a0));
        asm("mov.b64 {%0, %1}, %2;" : "=f"(r2), "=f"(r3) : "l"(a1));
        s_all = (r0 + r1) + (r2 + r3);
    }

    // ---- 100-group / 10-group / target terms ----
    float s100 = 0.f, s10 = 0.f, xt = 0.f;
    {
        const int j = g100lo + lane * 4;                 // only lanes 0..24 contribute
        const float vals[4] = {v100.x, v100.y, v100.z, v100.w};
#pragma unroll
        for (int k = 0; k < 4; ++k) {
            const float x = vals[k];
            const int jj = j + k;
            s100 += x;
            s10  += ((unsigned)(jj - g10lo) < 10u) ? x : 0.f;
            xt   += (jj == t) ? x : 0.f;
        }
    }

    float win = 0.5f * s_all + 0.25f * s100 + 0.125f * (s10 + xt);
#pragma unroll
    for (int off = 16; off; off >>= 1)
        win += __shfl_xor_sync(0xffffffffu, win, off);

    __shared__ float ssum[ROWS_PER_BLOCK];
    __shared__ bool is_last;
    if (lane == 0) ssum[warp] = 1.0f - win;
    __syncthreads();

    if (threadIdx.x == 0) {
        float acc = 0.f;
#pragma unroll
        for (int w = 0; w < ROWS_PER_BLOCK; ++w) acc += ssum[w];
        g_partials[blockIdx.x] = acc;
        __threadfence();
        unsigned int old = atomicAdd(&g_count, 1u);
        is_last = (old == (unsigned)(NBLOCKS - 1));
    }
    __syncthreads();

    // ---- Last block: deterministic fixed-order final reduction ----
    if (is_last) {
        __shared__ float fs[BLOCK_THREADS];
        float a = 0.f;
#pragma unroll
        for (int i = 0; i < NBLOCKS / BLOCK_THREADS; ++i)   // 16 each, fixed order
            a += g_partials[threadIdx.x + i * BLOCK_THREADS];
        fs[threadIdx.x] = a;
        __syncthreads();
#pragma unroll
        for (int stride = BLOCK_THREADS / 2; stride >= 1; stride >>= 1) {
            if (threadIdx.x < stride) fs[threadIdx.x] += fs[threadIdx.x + stride];
            __syncthreads();
        }
        if (threadIdx.x == 0) {
            out[0] = fs[0];
            g_count = 0u;          // reset for next graph replay
        }
    }
}

extern "C" void kernel_launch(void* const* d_in, const int* in_sizes, int n_in,
                              void* d_out, int out_size) {
    const float* outputs = (const float*)d_in[0];   // [32768, 1000] f32
    const int*   target  = (const int*)d_in[1];     // [32768] i32
    float* out = (float*)d_out;                     // scalar f32

    hloss_fused<<<NBLOCKS, BLOCK_THREADS>>>(outputs, target, out);
}

// round 4
// speedup vs baseline: 1.1784x; 1.1784x over previous
#include <cuda_runtime.h>

// Heirachical_Loss: loss = sum_i (1 - win_i)
// win_i = 0.5*S_all + 0.25*S100 + 0.125*S10 + 0.125*x[i,t]
// B=32768 rows, C=1000 fp32. HBM-streaming bound.
// Single-wave persistent: 1024 blocks x 8 warps x 4 rows/warp.
// Lane partials accumulated across rows; one warp-reduce total.

#define NROWS 32768
#define NCOLS 1000
#define NBLOCKS 1024
#define BLOCK_THREADS 256
#define WARPS_PER_BLOCK 8
#define ROWS_PER_WARP 4          // 1024*8*4 = 32768

__device__ float g_partials[NBLOCKS];
__device__ unsigned int g_count;          // zero-init; reset by last block each call

#define ADD_F32X2(acc, v) \
    asm("add.rn.f32x2 %0, %0, %1;" : "+l"(acc) : "l"(v))

__global__ void __launch_bounds__(BLOCK_THREADS, 7)    // <=36 regs, occ 7: 1024 blocks = 1 wave
hloss_fused(const float* __restrict__ outputs, const int* __restrict__ target,
            float* __restrict__ out) {
    const int warp = threadIdx.x >> 5;
    const int lane = threadIdx.x & 31;

    // lane partial accumulators, carried across all 4 rows
    unsigned long long a0 = 0ull, a1 = 0ull;    // packed f32x2: s_all
    float s100 = 0.f, s10 = 0.f, st = 0.f;

#pragma unroll
    for (int it = 0; it < ROWS_PER_WARP; ++it) {
        const int row = (it * NBLOCKS + blockIdx.x) * WARPS_PER_BLOCK + warp;
        const float* __restrict__ rowf = outputs + (size_t)row * NCOLS;
        const ulonglong2* __restrict__ rowp = reinterpret_cast<const ulonglong2*>(rowf);

        const int t = __ldg(target + row);
        const int g100lo = (t / 100) * 100;
        const int g10lo  = (t / 10)  * 10;

        ulonglong2 v[4];
        // batch A: float4 idx lane+0..lane+96 (MLP 4)
#pragma unroll
        for (int i = 0; i < 4; ++i) v[i] = rowp[lane + i * 32];
#pragma unroll
        for (int i = 0; i < 4; ++i) { ADD_F32X2(a0, v[i].x); ADD_F32X2(a1, v[i].y); }

        // batch B: idx lane+128..lane+192, plus tail 224+lane (lanes 0..25) (MLP 4)
#pragma unroll
        for (int i = 0; i < 3; ++i) v[i] = rowp[lane + (i + 4) * 32];
        v[3].x = 0ull; v[3].y = 0ull;
        if (lane < 26) v[3] = rowp[224 + lane];
#pragma unroll
        for (int i = 0; i < 4; ++i) { ADD_F32X2(a0, v[i].x); ADD_F32X2(a1, v[i].y); }

        // subset: the 100-group (25 float4s, lanes 0..24; lines already hot)
        if (lane < 25) {
            const float4 g = reinterpret_cast<const float4*>(rowf + g100lo)[lane];
            const int j = g100lo + lane * 4;
            const float vals[4] = {g.x, g.y, g.z, g.w};
#pragma unroll
            for (int k = 0; k < 4; ++k) {
                const float x = vals[k];
                const int jj = j + k;
                s100 += x;
                s10  += ((unsigned)(jj - g10lo) < 10u) ? x : 0.f;
                st   += (jj == t) ? x : 0.f;
            }
        }
    }

    // unpack packed accumulators, weight, single warp reduce
    float s_all;
    {
        float r0, r1, r2, r3;
        asm("mov.b64 {%0, %1}, %2;" : "=f"(r0), "=f"(r1) : "l"(a0));
        asm("mov.b64 {%0, %1}, %2;" : "=f"(r2), "=f"(r3) : "l"(a1));
        s_all = (r0 + r1) + (r2 + r3);
    }
    float win = 0.5f * s_all + 0.25f * s100 + 0.125f * (s10 + st);
#pragma unroll
    for (int off = 16; off; off >>= 1)
        win += __shfl_xor_sync(0xffffffffu, win, off);

    __shared__ float ssum[WARPS_PER_BLOCK];
    __shared__ bool is_last;
    if (lane == 0) ssum[warp] = (float)ROWS_PER_WARP - win;   // 4 rows' (1 - win_i)
    __syncthreads();

    if (threadIdx.x == 0) {
        float acc = 0.f;
#pragma unroll
        for (int w = 0; w < WARPS_PER_BLOCK; ++w) acc += ssum[w];
        g_partials[blockIdx.x] = acc;
        __threadfence();
        unsigned int old = atomicAdd(&g_count, 1u);
        is_last = (old == (unsigned)(NBLOCKS - 1));
    }
    __syncthreads();

    // last block: deterministic fixed-order final reduction of 1024 partials
    if (is_last) {
        __shared__ float fs[BLOCK_THREADS];
        float a = 0.f;
#pragma unroll
        for (int i = 0; i < NBLOCKS / BLOCK_THREADS; ++i)    // 4 each, fixed order
            a += g_partials[threadIdx.x + i * BLOCK_THREADS];
        fs[threadIdx.x] = a;
        __syncthreads();
#pragma unroll
        for (int stride = BLOCK_THREADS / 2; stride >= 1; stride >>= 1) {
            if (threadIdx.x < stride) fs[threadIdx.x] += fs[threadIdx.x + stride];
            __syncthreads();
        }
        if (threadIdx.x == 0) {
            out[0] = fs[0];
            g_count = 0u;         // reset for next graph replay
        }
    }
}

extern "C" void kernel_launch(void* const* d_in, const int* in_sizes, int n_in,
                              void* d_out, int out_size) {
    const float* outputs = (const float*)d_in[0];   // [32768, 1000] f32
    const int*   target  = (const int*)d_in[1];     // [32768] i32
    float* out = (float*)d_out;                     // scalar f32

    hloss_fused<<<NBLOCKS, BLOCK_THREADS>>>(outputs, target, out);
}